// round 7
// baseline (speedup 1.0000x reference)
#include <cuda_runtime.h>
#include <cstdint>
#include <cstddef>

#define T_N   1024
#define B_N   64
#define V_N   32000
#define H_N   512

#define GC    32                 // col-members per group
#define GB    4                  // independent batch-groups
#define GRID_R (GC * GB)         // 128 CTAs
#define BPG   16                 // batches per group
#define CPM   16                 // cols per member
#define NTHR  256

// ---------------- persistent device scratch ----------------
__device__ float    g_embW0[(size_t)V_N * H_N];   // emb @ Wih0^T + bih0 + bhh0
__device__ float    g_h0[2][B_N * H_N];
__device__ float    g_h1[2][B_N * H_N];
__device__ unsigned g_flag0[GRID_R * 8];          // "h0[s-1] stored" flags (32B stride)
__device__ unsigned g_flag1[GRID_R * 8];          // "h1[s-2] stored" flags

// ---------------- reset: deterministic per launch / graph replay ----------------
__global__ void reset_kernel() {
    int i = blockIdx.x * blockDim.x + threadIdx.x;
    if (i < B_N * H_N) {
        g_h0[0][i] = 0.f; g_h0[1][i] = 0.f;
        g_h1[0][i] = 0.f; g_h1[1][i] = 0.f;
    }
    if (i < GRID_R * 8) { g_flag0[i] = 0u; g_flag1[i] = 0u; }
}

// ---------------- embW0[v][h] = emb[v]·Wih0[h] + bih0[h] + bhh0[h] ----------------
__global__ __launch_bounds__(256) void embw_kernel(const float* __restrict__ A,
                                                   const float* __restrict__ W,
                                                   const float* __restrict__ bih,
                                                   const float* __restrict__ bhh) {
    __shared__ float As[8][132];
    __shared__ float Ws[8][132];
    const int tid   = threadIdx.x;
    const int hBase = blockIdx.x * 128;
    const int vBase = blockIdx.y * 128;
    const int lRow  = tid >> 1;
    const int lCol  = (tid & 1) * 4;
    const int tx    = tid & 15;
    const int ty    = tid >> 4;

    const float4* Ap = (const float4*)(A + (size_t)(vBase + lRow) * H_N + lCol);
    const float4* Wp = (const float4*)(W + (size_t)(hBase + lRow) * H_N + lCol);

    float acc[8][8];
#pragma unroll
    for (int i = 0; i < 8; i++)
#pragma unroll
        for (int j = 0; j < 8; j++) acc[i][j] = 0.f;

    float4 av = Ap[0];
    float4 wv = Wp[0];

    for (int k0 = 0; k0 < 512; k0 += 8) {
        __syncthreads();
        As[lCol + 0][lRow] = av.x; As[lCol + 1][lRow] = av.y;
        As[lCol + 2][lRow] = av.z; As[lCol + 3][lRow] = av.w;
        Ws[lCol + 0][lRow] = wv.x; Ws[lCol + 1][lRow] = wv.y;
        Ws[lCol + 2][lRow] = wv.z; Ws[lCol + 3][lRow] = wv.w;
        __syncthreads();
        if (k0 + 8 < 512) {
            av = Ap[(k0 + 8) >> 2];
            wv = Wp[(k0 + 8) >> 2];
        }
#pragma unroll
        for (int k = 0; k < 8; k++) {
            float a[8], w[8];
            *(float4*)&a[0] = *(const float4*)&As[k][ty * 8];
            *(float4*)&a[4] = *(const float4*)&As[k][ty * 8 + 4];
            *(float4*)&w[0] = *(const float4*)&Ws[k][tx * 8];
            *(float4*)&w[4] = *(const float4*)&Ws[k][tx * 8 + 4];
#pragma unroll
            for (int i = 0; i < 8; i++)
#pragma unroll
                for (int j = 0; j < 8; j++) acc[i][j] += a[i] * w[j];
        }
    }

#pragma unroll
    for (int i = 0; i < 8; i++) {
        const int v = vBase + ty * 8 + i;
        float* orow = &g_embW0[(size_t)v * H_N + hBase + tx * 8];
        float o[8];
#pragma unroll
        for (int j = 0; j < 8; j++) {
            int h = hBase + tx * 8 + j;
            o[j] = acc[i][j] + __ldg(&bih[h]) + __ldg(&bhh[h]);
        }
        *(float4*)&orow[0] = *(float4*)&o[0];
        *(float4*)&orow[4] = *(float4*)&o[4];
    }
}

// ---------------- packed-fp32 helpers ----------------
typedef unsigned long long u64;
__device__ __forceinline__ u64 ffma2(u64 a, u64 b, u64 c) {
    u64 d;
    asm("fma.rn.f32x2 %0, %1, %2, %3;" : "=l"(d) : "l"(a), "l"(b), "l"(c));
    return d;
}
__device__ __forceinline__ float unpack_sum(u64 a) {
    float lo, hi;
    asm("mov.b64 {%0, %1}, %2;" : "=f"(lo), "=f"(hi) : "l"(a));
    return lo + hi;
}

// ---------------- persistent recurrence kernel (batch-grouped) ----------------
// SMEM floats: W0[8192] WA[8192] WB[8192] Hs0[8192] Hs1[8192] Rs0[4352] Rs1[4352] b1[16]
#define OFF_W0 0
#define OFF_WA 8192
#define OFF_WB 16384
#define OFF_H0 24576
#define OFF_H1 32768
#define OFF_R0 40960
#define OFF_R1 (OFF_R0 + 4352)
#define OFF_B1 (OFF_R1 + 4352)
#define SMEM_FLOATS (OFF_B1 + 16)
#define SMEM_BYTES  (SMEM_FLOATS * 4)

__global__ __launch_bounds__(NTHR, 1) void rnn_kernel(const int*   __restrict__ input,
                                                      const float* __restrict__ Whh0,
                                                      const float* __restrict__ Wih1,
                                                      const float* __restrict__ Whh1,
                                                      const float* __restrict__ bih1,
                                                      const float* __restrict__ bhh1,
                                                      float*       __restrict__ out) {
    extern __shared__ float smem[];
    float* W0s = smem + OFF_W0;
    float* WAs = smem + OFF_WA;
    float* WBs = smem + OFF_WB;
    float* Hs0 = smem + OFF_H0;
    float* Hs1 = smem + OFF_H1;
    float* Rs0 = smem + OFF_R0;
    float* Rs1 = smem + OFF_R1;
    float* b1s = smem + OFF_B1;

    const int tid  = threadIdx.x;
    const int cid  = blockIdx.x;
    const int m    = cid & (GC - 1);   // member: cols [m*16, m*16+16)
    const int grp  = cid >> 5;         // group: batches [grp*16, grp*16+16)
    const int gb16 = grp * BPG;
    const int w    = tid >> 5;
    const int lane = tid & 31;
    const int o    = w >> 2;           // batch-oct (0..1)
    const int cc   = w & 3;            // col-quad  (0..3)

    // ---- preload weight slices: rows [m*16, m*16+16) ----
    {
        const float4* s0 = (const float4*)Whh0 + (size_t)m * 2048;
        const float4* s1 = (const float4*)Wih1 + (size_t)m * 2048;
        const float4* s2 = (const float4*)Whh1 + (size_t)m * 2048;
        float4* d0 = (float4*)W0s; float4* d1 = (float4*)WAs; float4* d2 = (float4*)WBs;
        for (int r = tid; r < 2048; r += NTHR) {
            d0[r] = __ldg(&s0[r]);
            d1[r] = __ldg(&s1[r]);
            d2[r] = __ldg(&s2[r]);
        }
        if (tid < CPM) b1s[tid] = __ldg(&bih1[m * CPM + tid]) + __ldg(&bhh1[m * CPM + tid]);
    }
    __syncthreads();

    // output decode: thread tid owns Rs row tid
    const int w_o    = tid >> 5;
    const int i_o    = (tid >> 2) & 7;
    const int c_o    = tid & 3;
    const int b_out  = gb16 + (w_o >> 2) * 8 + i_o;
    const int c_loc  = (w_o & 3) * 4 + c_o;
    const int c_glob = m * CPM + c_loc;

    const ulonglong2* W0u = (const ulonglong2*)W0s;
    const ulonglong2* WAu = (const ulonglong2*)WAs;
    const ulonglong2* WBu = (const ulonglong2*)WBs;
    const ulonglong2* H0u = (const ulonglong2*)Hs0;
    const ulonglong2* H1u = (const ulonglong2*)Hs1;
    const unsigned sd0 = (unsigned)__cvta_generic_to_shared(Hs0);
    const unsigned sd1 = (unsigned)__cvta_generic_to_shared(Hs1);

    u64 acc0[8][4], accA[8][4];

    // fused pass-1 chunk: one k-quarter J; hv shared across both weight sets
#define MMA1_CHUNK(J)                                                            \
    {                                                                            \
        ulonglong2 w0q[4], waq[4];                                               \
        _Pragma("unroll")                                                        \
        for (int c = 0; c < 4; c++) {                                            \
            int row = cc * 4 + c;                                                \
            w0q[c] = W0u[row * 128 + (J) * 32 + lane];                           \
            waq[c] = WAu[row * 128 + (J) * 32 + lane];                           \
        }                                                                        \
        _Pragma("unroll")                                                        \
        for (int i = 0; i < 8; i++) {                                            \
            ulonglong2 hv = H0u[(J) * 512 + (o * 8 + i) * 32 + lane];            \
            _Pragma("unroll")                                                    \
            for (int c = 0; c < 4; c++) {                                        \
                acc0[i][c] = ffma2(hv.x, w0q[c].x, acc0[i][c]);                  \
                acc0[i][c] = ffma2(hv.y, w0q[c].y, acc0[i][c]);                  \
                accA[i][c] = ffma2(hv.x, waq[c].x, accA[i][c]);                  \
                accA[i][c] = ffma2(hv.y, waq[c].y, accA[i][c]);                  \
            }                                                                    \
        }                                                                        \
    }

    // pass-2 chunk: Whh1 · h1[s-3] accumulated into accA
#define MMA2_CHUNK(J)                                                            \
    {                                                                            \
        ulonglong2 wbq[4];                                                       \
        _Pragma("unroll")                                                        \
        for (int c = 0; c < 4; c++)                                              \
            wbq[c] = WBu[(cc * 4 + c) * 128 + (J) * 32 + lane];                  \
        _Pragma("unroll")                                                        \
        for (int i = 0; i < 8; i++) {                                            \
            ulonglong2 hv = H1u[(J) * 512 + (o * 8 + i) * 32 + lane];            \
            _Pragma("unroll")                                                    \
            for (int c = 0; c < 4; c++) {                                        \
                accA[i][c] = ffma2(hv.x, wbq[c].x, accA[i][c]);                  \
                accA[i][c] = ffma2(hv.y, wbq[c].y, accA[i][c]);                  \
            }                                                                    \
        }                                                                        \
    }

    // shfl pre-reduce ACC -> RS (lanes 0..15 write rows of 16, stride 17)
#define REDUCE_TO(RS, ACC)                                                       \
    _Pragma("unroll")                                                            \
    for (int i = 0; i < 8; i++)                                                  \
        _Pragma("unroll")                                                        \
        for (int c = 0; c < 4; c++) {                                            \
            float v = unpack_sum(ACC[i][c]);                                     \
            v += __shfl_xor_sync(0xffffffffu, v, 16);                            \
            if (lane < 16) (RS)[(w * 32 + i * 4 + c) * 17 + lane] = v;           \
        }

    // stage one k-half (Q2 = 0/1, quarters 2*Q2..2*Q2+1) of a state buffer
#define STAGE_HALF(SD, SRC, Q2)                                                  \
    {                                                                            \
        _Pragma("unroll")                                                        \
        for (int r = 0; r < 4; r++) {                                            \
            int l2 = r * NTHR + tid;             /* 0..1023 within half */       \
            int j  = (Q2) * 2 + (l2 >> 9);       /* k-quarter */                 \
            int lq = l2 & 511;                                                   \
            int b_l = lq >> 5;                                                   \
            int c4  = lq & 31;                                                   \
            size_t srcf4 = (size_t)(gb16 + b_l) * 128 + j * 32 + c4;             \
            asm volatile("cp.async.cg.shared.global [%0], [%1], 16;\n"           \
                         :: "r"((SD) + (j * 512 + lq) * 16), "l"((SRC) + srcf4 * 4)); \
        }                                                                        \
        asm volatile("cp.async.commit_group;\n");                                \
    }

    // poll 32 member flags (warp 0), then gpu-scope fence
#define WAIT_FLAGS(FARR, VAL)                                                    \
    if (w == 0) {                                                                \
        const unsigned* fp = &(FARR)[(grp * GC + lane) * 8];                     \
        unsigned v;                                                              \
        do {                                                                     \
            asm volatile("ld.relaxed.gpu.global.u32 %0, [%1];"                   \
                         : "=r"(v) : "l"(fp) : "memory");                        \
        } while (__any_sync(0xffffffffu, v < (unsigned)(VAL)));                  \
        __threadfence();                                                         \
    }

#define SET_FLAG(FARR, VAL)                                                      \
    if (tid == 0) {                                                              \
        __threadfence();                                                         \
        asm volatile("st.relaxed.gpu.global.u32 [%0], %1;"                       \
                     :: "l"(&(FARR)[cid * 8]), "r"((unsigned)(VAL)) : "memory"); \
    }

    for (int s = 1; s <= T_N + 1; s++) {
        const bool doH0 = (s <= T_N);
        const bool doH1 = (s >= 2);

        // ---- gather input-projection value early (independent) ----
        float xw = 0.f;
        if (doH0) {
            int tok = __ldg(&input[(s - 1) * B_N + b_out]);
            xw = __ldcg(&g_embW0[(size_t)tok * H_N + c_glob]);
        }

        // ---- wait peers' h0[s-2] (flag0 >= s-1; usually already set) ----
        WAIT_FLAGS(g_flag0, s - 1)
        __syncthreads();

        // ---- stage h0[s-2]: 2 commit groups ----
        {
            const float* src = g_h0[s & 1];
            STAGE_HALF(sd0, src, 0)
            STAGE_HALF(sd0, src, 1)
        }

#pragma unroll
        for (int i = 0; i < 8; i++)
#pragma unroll
            for (int c = 0; c < 4; c++) { acc0[i][c] = 0ull; accA[i][c] = 0ull; }

        // ---- pass 1 (fused Whh0 + Wih1 on h0[s-2]) ----
        asm volatile("cp.async.wait_group 1;\n" ::: "memory");
        __syncthreads();
        MMA1_CHUNK(0)
        MMA1_CHUNK(1)
        asm volatile("cp.async.wait_group 0;\n" ::: "memory");
        __syncthreads();
        MMA1_CHUNK(2)
        MMA1_CHUNK(3)

        // ---- reduce0 + h0[s-1] store + EARLY flag0 publish ----
        REDUCE_TO(Rs0, acc0)
        __syncthreads();
        if (doH0) {
            float ssum = 0.f;
#pragma unroll
            for (int l = 0; l < 16; l++) ssum += Rs0[tid * 17 + l];
            __stcg(&g_h0[(s - 1) & 1][b_out * H_N + c_glob], tanhf(ssum + xw));
        }
        __syncthreads();
        SET_FLAG(g_flag0, s)

        // ---- wait peers' h1[s-3] (flag1 >= s-1; large slack) then stage ----
        WAIT_FLAGS(g_flag1, s - 1)
        __syncthreads();
        {
            const float* src = g_h1[(s + 1) & 1];
            STAGE_HALF(sd1, src, 0)
            STAGE_HALF(sd1, src, 1)
        }

        // ---- pass 2 (Whh1 on h1[s-3]) ----
        asm volatile("cp.async.wait_group 1;\n" ::: "memory");
        __syncthreads();
        MMA2_CHUNK(0)
        MMA2_CHUNK(1)
        asm volatile("cp.async.wait_group 0;\n" ::: "memory");
        __syncthreads();
        MMA2_CHUNK(2)
        MMA2_CHUNK(3)

        // ---- reduce1 + h1[s-2] store + flag1 publish ----
        REDUCE_TO(Rs1, accA)
        __syncthreads();
        if (doH1) {
            float ssum = 0.f;
#pragma unroll
            for (int l = 0; l < 16; l++) ssum += Rs1[tid * 17 + l];
            float v = tanhf(ssum + b1s[c_loc]);
            __stcg(&g_h1[s & 1][b_out * H_N + c_glob], v);
            if (s == T_N + 1) __stcg(&out[b_out * H_N + c_glob], v);
        }
        __syncthreads();
        SET_FLAG(g_flag1, s)
    }
#undef MMA1_CHUNK
#undef MMA2_CHUNK
#undef REDUCE_TO
#undef STAGE_HALF
#undef WAIT_FLAGS
#undef SET_FLAG
}

// ---------------- launch ----------------
extern "C" void kernel_launch(void* const* d_in, const int* in_sizes, int n_in,
                              void* d_out, int out_size) {
    const int*   input = (const int*)  d_in[0];
    const float* emb   = (const float*)d_in[1];
    const float* Wih0  = (const float*)d_in[2];
    const float* Whh0  = (const float*)d_in[3];
    const float* bih0  = (const float*)d_in[4];
    const float* bhh0  = (const float*)d_in[5];
    const float* Wih1  = (const float*)d_in[6];
    const float* Whh1  = (const float*)d_in[7];
    const float* bih1  = (const float*)d_in[8];
    const float* bhh1  = (const float*)d_in[9];
    float* out = (float*)d_out;

    cudaFuncSetAttribute(rnn_kernel, cudaFuncAttributeMaxDynamicSharedMemorySize, SMEM_BYTES);

    reset_kernel<<<(B_N * H_N + 255) / 256, 256>>>();
    embw_kernel<<<dim3(H_N / 128, V_N / 128), 256>>>(emb, Wih0, bih0, bhh0);
    rnn_kernel<<<GRID_R, NTHR, SMEM_BYTES>>>(input, Whh0, Wih1, Whh1, bih1, bhh1, out);
}

// round 8
// speedup vs baseline: 1.0698x; 1.0698x over previous
#include <cuda_runtime.h>
#include <cstdint>
#include <cstddef>

#define T_N   1024
#define B_N   64
#define V_N   32000
#define H_N   512

#define GC    64                 // col-members per group (8 cols each)
#define GB    4                  // independent batch-groups
#define GRID_R (GC * GB)         // 256 CTAs, 2 per SM
#define BPG   16                 // batches per group
#define CPM   8                  // cols per member
#define NTHR  256

// ---------------- persistent device scratch ----------------
__device__ float    g_embW0[(size_t)V_N * H_N];   // emb @ Wih0^T + bih0 + bhh0
__device__ float    g_h0[2][B_N * H_N];
__device__ float    g_h1[2][B_N * H_N];
__device__ unsigned g_flag[GRID_R * 8];           // per-CTA step flags (32B stride)

// ---------------- reset: deterministic per launch / graph replay ----------------
__global__ void reset_kernel() {
    int i = blockIdx.x * blockDim.x + threadIdx.x;
    if (i < B_N * H_N) {
        g_h0[0][i] = 0.f; g_h0[1][i] = 0.f;
        g_h1[0][i] = 0.f; g_h1[1][i] = 0.f;
    }
    if (i < GRID_R * 8) g_flag[i] = 0u;
}

// ---------------- embW0[v][h] = emb[v]·Wih0[h] + bih0[h] + bhh0[h] ----------------
__global__ __launch_bounds__(256) void embw_kernel(const float* __restrict__ A,
                                                   const float* __restrict__ W,
                                                   const float* __restrict__ bih,
                                                   const float* __restrict__ bhh) {
    __shared__ float As[8][132];
    __shared__ float Ws[8][132];
    const int tid   = threadIdx.x;
    const int hBase = blockIdx.x * 128;
    const int vBase = blockIdx.y * 128;
    const int lRow  = tid >> 1;
    const int lCol  = (tid & 1) * 4;
    const int tx    = tid & 15;
    const int ty    = tid >> 4;

    const float4* Ap = (const float4*)(A + (size_t)(vBase + lRow) * H_N + lCol);
    const float4* Wp = (const float4*)(W + (size_t)(hBase + lRow) * H_N + lCol);

    float acc[8][8];
#pragma unroll
    for (int i = 0; i < 8; i++)
#pragma unroll
        for (int j = 0; j < 8; j++) acc[i][j] = 0.f;

    float4 av = Ap[0];
    float4 wv = Wp[0];

    for (int k0 = 0; k0 < 512; k0 += 8) {
        __syncthreads();
        As[lCol + 0][lRow] = av.x; As[lCol + 1][lRow] = av.y;
        As[lCol + 2][lRow] = av.z; As[lCol + 3][lRow] = av.w;
        Ws[lCol + 0][lRow] = wv.x; Ws[lCol + 1][lRow] = wv.y;
        Ws[lCol + 2][lRow] = wv.z; Ws[lCol + 3][lRow] = wv.w;
        __syncthreads();
        if (k0 + 8 < 512) {
            av = Ap[(k0 + 8) >> 2];
            wv = Wp[(k0 + 8) >> 2];
        }
#pragma unroll
        for (int k = 0; k < 8; k++) {
            float a[8], w[8];
            *(float4*)&a[0] = *(const float4*)&As[k][ty * 8];
            *(float4*)&a[4] = *(const float4*)&As[k][ty * 8 + 4];
            *(float4*)&w[0] = *(const float4*)&Ws[k][tx * 8];
            *(float4*)&w[4] = *(const float4*)&Ws[k][tx * 8 + 4];
#pragma unroll
            for (int i = 0; i < 8; i++)
#pragma unroll
                for (int j = 0; j < 8; j++) acc[i][j] += a[i] * w[j];
        }
    }

#pragma unroll
    for (int i = 0; i < 8; i++) {
        const int v = vBase + ty * 8 + i;
        float* orow = &g_embW0[(size_t)v * H_N + hBase + tx * 8];
        float o[8];
#pragma unroll
        for (int j = 0; j < 8; j++) {
            int h = hBase + tx * 8 + j;
            o[j] = acc[i][j] + __ldg(&bih[h]) + __ldg(&bhh[h]);
        }
        *(float4*)&orow[0] = *(float4*)&o[0];
        *(float4*)&orow[4] = *(float4*)&o[4];
    }
}

// ---------------- persistent recurrence kernel (2 CTAs/SM) ----------------
// SMEM floats: W0[4096] WA[4096] WB[4096] Hs[8192] Rs0[2176] Rs1[2176] b1[8]
#define OFF_W0 0
#define OFF_WA 4096
#define OFF_WB 8192
#define OFF_HS 12288
#define OFF_R0 20480
#define OFF_R1 (OFF_R0 + 2176)
#define OFF_B1 (OFF_R1 + 2176)
#define SMEM_FLOATS (OFF_B1 + 8)
#define SMEM_BYTES  (SMEM_FLOATS * 4)       // ~99.4 KB -> 2 CTAs/SM

__global__ __launch_bounds__(NTHR, 2) void rnn_kernel(const int*   __restrict__ input,
                                                      const float* __restrict__ Whh0,
                                                      const float* __restrict__ Wih1,
                                                      const float* __restrict__ Whh1,
                                                      const float* __restrict__ bih1,
                                                      const float* __restrict__ bhh1,
                                                      float*       __restrict__ out) {
    extern __shared__ float smem[];
    float* W0s = smem + OFF_W0;
    float* WAs = smem + OFF_WA;
    float* WBs = smem + OFF_WB;
    float* Hs  = smem + OFF_HS;
    float* Rs0 = smem + OFF_R0;
    float* Rs1 = smem + OFF_R1;
    float* b1s = smem + OFF_B1;

    const int tid  = threadIdx.x;
    const int cid  = blockIdx.x;
    const int m    = cid & (GC - 1);   // member: cols [m*8, m*8+8)
    const int grp  = cid >> 6;         // group: batches [grp*16, grp*16+16)
    const int gb16 = grp * BPG;
    const int w    = tid >> 5;
    const int lane = tid & 31;
    const int o    = w >> 2;           // batch-oct (0..1)
    const int cc   = w & 3;            // col-pair  (0..3), cols cc*2..cc*2+1

    // ---- preload weight slices: rows [m*8, m*8+8) of each matrix ----
    {
        const float4* s0 = (const float4*)Whh0 + (size_t)m * 1024;
        const float4* s1 = (const float4*)Wih1 + (size_t)m * 1024;
        const float4* s2 = (const float4*)Whh1 + (size_t)m * 1024;
        float4* d0 = (float4*)W0s; float4* d1 = (float4*)WAs; float4* d2 = (float4*)WBs;
        for (int r = tid; r < 1024; r += NTHR) {
            d0[r] = __ldg(&s0[r]);
            d1[r] = __ldg(&s1[r]);
            d2[r] = __ldg(&s2[r]);
        }
        if (tid < CPM) b1s[tid] = __ldg(&bih1[m * CPM + tid]) + __ldg(&bhh1[m * CPM + tid]);
    }
    __syncthreads();

    // read-phase decode: thread tid<128 owns output row tid
    const int b_out  = gb16 + (tid >> 3);
    const int c_glob = m * CPM + (tid & 7);

    const float4* W04 = (const float4*)W0s;
    const float4* WA4 = (const float4*)WAs;
    const float4* WB4 = (const float4*)WBs;
    const float4* Hs4 = (const float4*)Hs;
    const unsigned sdh = (unsigned)__cvta_generic_to_shared(Hs);

    float acc0[8][2], accA[8][2];

    // fused pass-1 chunk (k-quarter J): Whh0 + Wih1 share each hv load
#define MMA1_CHUNK(J)                                                            \
    {                                                                            \
        float4 w0q[2], waq[2];                                                   \
        _Pragma("unroll")                                                        \
        for (int c = 0; c < 2; c++) {                                            \
            int row = cc * 2 + c;                                                \
            w0q[c] = W04[row * 128 + (J) * 32 + lane];                           \
            waq[c] = WA4[row * 128 + (J) * 32 + lane];                           \
        }                                                                        \
        _Pragma("unroll")                                                        \
        for (int i = 0; i < 8; i++) {                                            \
            float4 hv = Hs4[(o * 8 + i) * 128 + (J) * 32 + lane];                \
            _Pragma("unroll")                                                    \
            for (int c = 0; c < 2; c++) {                                        \
                acc0[i][c] += hv.x * w0q[c].x + hv.y * w0q[c].y                  \
                            + hv.z * w0q[c].z + hv.w * w0q[c].w;                 \
                accA[i][c] += hv.x * waq[c].x + hv.y * waq[c].y                  \
                            + hv.z * waq[c].z + hv.w * waq[c].w;                 \
            }                                                                    \
        }                                                                        \
    }

    // pass-2 chunk: Whh1 · h1[s-3] (restaged into Hs) into accA
#define MMA2_CHUNK(J)                                                            \
    {                                                                            \
        float4 wbq[2];                                                           \
        _Pragma("unroll")                                                        \
        for (int c = 0; c < 2; c++)                                              \
            wbq[c] = WB4[(cc * 2 + c) * 128 + (J) * 32 + lane];                  \
        _Pragma("unroll")                                                        \
        for (int i = 0; i < 8; i++) {                                            \
            float4 hv = Hs4[(o * 8 + i) * 128 + (J) * 32 + lane];                \
            _Pragma("unroll")                                                    \
            for (int c = 0; c < 2; c++)                                          \
                accA[i][c] += hv.x * wbq[c].x + hv.y * wbq[c].y                  \
                            + hv.z * wbq[c].z + hv.w * wbq[c].w;                 \
        }                                                                        \
    }

    // shfl-16 pre-reduce ACC -> RS rows of 16 (stride 17, conflict-free)
#define REDUCE_TO(RS, ACC)                                                       \
    _Pragma("unroll")                                                            \
    for (int i = 0; i < 8; i++)                                                  \
        _Pragma("unroll")                                                        \
        for (int c = 0; c < 2; c++) {                                            \
            float v = ACC[i][c];                                                 \
            v += __shfl_xor_sync(0xffffffffu, v, 16);                            \
            if (lane < 16)                                                       \
                (RS)[((o * 8 + i) * 8 + cc * 2 + c) * 17 + lane] = v;            \
        }

    // stage one k-half (Q=0/1) of a 16-row state block into Hs
#define STAGE_HALF(SRC, Q)                                                       \
    {                                                                            \
        _Pragma("unroll")                                                        \
        for (int r = 0; r < 4; r++) {                                            \
            int l   = r * NTHR + tid;          /* 0..1023 f4 within half */      \
            int b_l = l >> 6;                                                    \
            int c4  = l & 63;                                                    \
            size_t srcf4 = (size_t)(gb16 + b_l) * 128 + (Q) * 64 + c4;           \
            asm volatile("cp.async.cg.shared.global [%0], [%1], 16;\n"           \
                         :: "r"(sdh + (b_l * 128 + (Q) * 64 + c4) * 16),         \
                            "l"((SRC) + srcf4 * 4));                             \
        }                                                                        \
        asm volatile("cp.async.commit_group;\n");                                \
    }

    for (int s = 1; s <= T_N + 1; s++) {
        const bool doH0 = (s <= T_N);
        const bool doH1 = (s >= 2);

        // ---- gather input-projection value early (independent) ----
        float xw = 0.f;
        if (doH0 && tid < 128) {
            int tok = __ldg(&input[(s - 1) * B_N + b_out]);
            xw = __ldcg(&g_embW0[(size_t)tok * H_N + c_glob]);
        }

        // ---- barrier: wait all 64 members' flags >= s-1 (acquire polls) ----
        if (w == 0) {
            const unsigned* fa = &g_flag[(grp * GC + lane) * 8];
            const unsigned* fb = fa + 32 * 8;
            unsigned v1, v2;
            do {
                asm volatile("ld.acquire.gpu.global.u32 %0, [%1];"
                             : "=r"(v1) : "l"(fa) : "memory");
                asm volatile("ld.acquire.gpu.global.u32 %0, [%1];"
                             : "=r"(v2) : "l"(fb) : "memory");
            } while (__any_sync(0xffffffffu,
                                (v1 < (unsigned)(s - 1)) | (v2 < (unsigned)(s - 1))));
        }
        __syncthreads();

        // ---- stage h0[s-2] into Hs (2 commit groups) ----
        {
            const float* src = g_h0[s & 1];
            STAGE_HALF(src, 0)
            STAGE_HALF(src, 1)
        }

#pragma unroll
        for (int i = 0; i < 8; i++)
#pragma unroll
            for (int c = 0; c < 2; c++) { acc0[i][c] = 0.f; accA[i][c] = 0.f; }

        // ---- pass 1 (fused Whh0 + Wih1 on h0[s-2]) ----
        asm volatile("cp.async.wait_group 1;\n" ::: "memory");
        __syncthreads();
        MMA1_CHUNK(0)
        MMA1_CHUNK(1)
        asm volatile("cp.async.wait_group 0;\n" ::: "memory");
        __syncthreads();
        MMA1_CHUNK(2)
        MMA1_CHUNK(3)

        // ---- reduce0 write; the sync also closes all Hs reads of pass 1 ----
        REDUCE_TO(Rs0, acc0)
        __syncthreads();

        // ---- restage Hs with h1[s-3]; latency hides behind reduce0 tail ----
        {
            const float* src = g_h1[(s + 1) & 1];
            STAGE_HALF(src, 0)
            STAGE_HALF(src, 1)
        }

        // ---- reduce0 read + h0[s-1] store (overlaps h1 staging) ----
        if (doH0 && tid < 128) {
            float ssum = 0.f;
#pragma unroll
            for (int l = 0; l < 16; l++) ssum += Rs0[tid * 17 + l];
            __stcg(&g_h0[(s - 1) & 1][b_out * H_N + c_glob], tanhf(ssum + xw));
        }

        // ---- pass 2 (Whh1 on h1[s-3]) ----
        asm volatile("cp.async.wait_group 1;\n" ::: "memory");
        __syncthreads();
        MMA2_CHUNK(0)
        MMA2_CHUNK(1)
        asm volatile("cp.async.wait_group 0;\n" ::: "memory");
        __syncthreads();
        MMA2_CHUNK(2)
        MMA2_CHUNK(3)

        // ---- reduce1 + h1[s-2] store ----
        REDUCE_TO(Rs1, accA)
        __syncthreads();
        if (doH1 && tid < 128) {
            float ssum = 0.f;
#pragma unroll
            for (int l = 0; l < 16; l++) ssum += Rs1[tid * 17 + l];
            float v = tanhf(ssum + b1s[tid & 7]);
            __stcg(&g_h1[s & 1][b_out * H_N + c_glob], v);
            if (s == T_N + 1) __stcg(&out[b_out * H_N + c_glob], v);
        }

        // ---- publish step (release store; syncthreads gives intra-CTA hb) ----
        __syncthreads();
        if (tid == 0)
            asm volatile("st.release.gpu.global.u32 [%0], %1;"
                         :: "l"(&g_flag[cid * 8]), "r"((unsigned)s) : "memory");
    }
#undef MMA1_CHUNK
#undef MMA2_CHUNK
#undef REDUCE_TO
#undef STAGE_HALF
}

// ---------------- launch ----------------
extern "C" void kernel_launch(void* const* d_in, const int* in_sizes, int n_in,
                              void* d_out, int out_size) {
    const int*   input = (const int*)  d_in[0];
    const float* emb   = (const float*)d_in[1];
    const float* Wih0  = (const float*)d_in[2];
    const float* Whh0  = (const float*)d_in[3];
    const float* bih0  = (const float*)d_in[4];
    const float* bhh0  = (const float*)d_in[5];
    const float* Wih1  = (const float*)d_in[6];
    const float* Whh1  = (const float*)d_in[7];
    const float* bih1  = (const float*)d_in[8];
    const float* bhh1  = (const float*)d_in[9];
    float* out = (float*)d_out;

    cudaFuncSetAttribute(rnn_kernel, cudaFuncAttributeMaxDynamicSharedMemorySize, SMEM_BYTES);

    reset_kernel<<<(B_N * H_N + 255) / 256, 256>>>();
    embw_kernel<<<dim3(H_N / 128, V_N / 128), 256>>>(emb, Wih0, bih0, bhh0);
    rnn_kernel<<<GRID_R, NTHR, SMEM_BYTES>>>(input, Whh0, Wih1, Whh1, bih1, bhh1, out);
}

// round 10
// speedup vs baseline: 1.1537x; 1.0784x over previous
#include <cuda_runtime.h>
#include <cstdint>
#include <cstddef>

#define T_N   1024
#define B_N   64
#define V_N   32000
#define H_N   512

#define GC    32                 // col-members per group
#define GB    4                  // independent batch-groups
#define GRID_R (GC * GB)         // 128 CTAs, 1 per SM
#define BPG   16                 // batches per group
#define CPM   16                 // cols per member
#define NTHR  256

// ---------------- persistent device scratch ----------------
__device__ float    g_embW0[(size_t)V_N * H_N];   // emb @ Wih0^T + bih0 + bhh0
__device__ float    g_h0[2][B_N * H_N];
__device__ float    g_h1[2][B_N * H_N];
__device__ unsigned g_flag[GRID_R * 8];           // per-CTA step flags (32B stride)

// ---------------- reset: deterministic per launch / graph replay ----------------
__global__ void reset_kernel() {
    int i = blockIdx.x * blockDim.x + threadIdx.x;
    if (i < B_N * H_N) {
        g_h0[0][i] = 0.f; g_h0[1][i] = 0.f;
        g_h1[0][i] = 0.f; g_h1[1][i] = 0.f;
    }
    if (i < GRID_R * 8) g_flag[i] = 0u;
}

// ---------------- embW0[v][h] = emb[v]·Wih0[h] + bih0[h] + bhh0[h] ----------------
__global__ __launch_bounds__(256) void embw_kernel(const float* __restrict__ A,
                                                   const float* __restrict__ W,
                                                   const float* __restrict__ bih,
                                                   const float* __restrict__ bhh) {
    __shared__ float As[8][132];
    __shared__ float Ws[8][132];
    const int tid   = threadIdx.x;
    const int hBase = blockIdx.x * 128;
    const int vBase = blockIdx.y * 128;
    const int lRow  = tid >> 1;
    const int lCol  = (tid & 1) * 4;
    const int tx    = tid & 15;
    const int ty    = tid >> 4;

    const float4* Ap = (const float4*)(A + (size_t)(vBase + lRow) * H_N + lCol);
    const float4* Wp = (const float4*)(W + (size_t)(hBase + lRow) * H_N + lCol);

    float acc[8][8];
#pragma unroll
    for (int i = 0; i < 8; i++)
#pragma unroll
        for (int j = 0; j < 8; j++) acc[i][j] = 0.f;

    float4 av = Ap[0];
    float4 wv = Wp[0];

    for (int k0 = 0; k0 < 512; k0 += 8) {
        __syncthreads();
        As[lCol + 0][lRow] = av.x; As[lCol + 1][lRow] = av.y;
        As[lCol + 2][lRow] = av.z; As[lCol + 3][lRow] = av.w;
        Ws[lCol + 0][lRow] = wv.x; Ws[lCol + 1][lRow] = wv.y;
        Ws[lCol + 2][lRow] = wv.z; Ws[lCol + 3][lRow] = wv.w;
        __syncthreads();
        if (k0 + 8 < 512) {
            av = Ap[(k0 + 8) >> 2];
            wv = Wp[(k0 + 8) >> 2];
        }
#pragma unroll
        for (int k = 0; k < 8; k++) {
            float a[8], w[8];
            *(float4*)&a[0] = *(const float4*)&As[k][ty * 8];
            *(float4*)&a[4] = *(const float4*)&As[k][ty * 8 + 4];
            *(float4*)&w[0] = *(const float4*)&Ws[k][tx * 8];
            *(float4*)&w[4] = *(const float4*)&Ws[k][tx * 8 + 4];
#pragma unroll
            for (int i = 0; i < 8; i++)
#pragma unroll
                for (int j = 0; j < 8; j++) acc[i][j] += a[i] * w[j];
        }
    }

#pragma unroll
    for (int i = 0; i < 8; i++) {
        const int v = vBase + ty * 8 + i;
        float* orow = &g_embW0[(size_t)v * H_N + hBase + tx * 8];
        float o[8];
#pragma unroll
        for (int j = 0; j < 8; j++) {
            int h = hBase + tx * 8 + j;
            o[j] = acc[i][j] + __ldg(&bih[h]) + __ldg(&bhh[h]);
        }
        *(float4*)&orow[0] = *(float4*)&o[0];
        *(float4*)&orow[4] = *(float4*)&o[4];
    }
}

// ---------------- packed-fp32 helpers ----------------
typedef unsigned long long u64;
__device__ __forceinline__ u64 ffma2(u64 a, u64 b, u64 c) {
    u64 d;
    asm("fma.rn.f32x2 %0, %1, %2, %3;" : "=l"(d) : "l"(a), "l"(b), "l"(c));
    return d;
}
__device__ __forceinline__ float unpack_sum(u64 a) {
    float lo, hi;
    asm("mov.b64 {%0, %1}, %2;" : "=f"(lo), "=f"(hi) : "l"(a));
    return lo + hi;
}

// ---------------- persistent recurrence kernel (1 CTA/SM, wide tiles) ----------------
// SMEM floats: W0[8192] WA[8192] WB[8192] Hs0[8192] Hs1[8192] Rs0[4352] Rs1[4352] b1[16]
#define OFF_W0 0
#define OFF_WA 8192
#define OFF_WB 16384
#define OFF_H0 24576
#define OFF_H1 32768
#define OFF_R0 40960
#define OFF_R1 (OFF_R0 + 4352)
#define OFF_B1 (OFF_R1 + 4352)
#define SMEM_FLOATS (OFF_B1 + 16)
#define SMEM_BYTES  (SMEM_FLOATS * 4)       // ~198.7 KB

__global__ __launch_bounds__(NTHR, 1) void rnn_kernel(const int*   __restrict__ input,
                                                      const float* __restrict__ Whh0,
                                                      const float* __restrict__ Wih1,
                                                      const float* __restrict__ Whh1,
                                                      const float* __restrict__ bih1,
                                                      const float* __restrict__ bhh1,
                                                      float*       __restrict__ out) {
    extern __shared__ float smem[];
    float* W0s = smem + OFF_W0;
    float* WAs = smem + OFF_WA;
    float* WBs = smem + OFF_WB;
    float* Hs0 = smem + OFF_H0;
    float* Hs1 = smem + OFF_H1;
    float* Rs0 = smem + OFF_R0;
    float* Rs1 = smem + OFF_R1;
    float* b1s = smem + OFF_B1;

    const int tid  = threadIdx.x;
    const int cid  = blockIdx.x;
    const int m    = cid & (GC - 1);   // member: cols [m*16, m*16+16)
    const int grp  = cid >> 5;         // group: batches [grp*16, grp*16+16)
    const int gb16 = grp * BPG;
    const int w    = tid >> 5;
    const int lane = tid & 31;
    const int o    = w >> 2;           // batch-oct (0..1)
    const int cq   = w & 3;            // col-quad  (0..3): cols cq*4..cq*4+3

    // ---- preload weight slices: rows [m*16, m*16+16) ----
    {
        const float4* s0 = (const float4*)Whh0 + (size_t)m * 2048;
        const float4* s1 = (const float4*)Wih1 + (size_t)m * 2048;
        const float4* s2 = (const float4*)Whh1 + (size_t)m * 2048;
        float4* d0 = (float4*)W0s; float4* d1 = (float4*)WAs; float4* d2 = (float4*)WBs;
        for (int r = tid; r < 2048; r += NTHR) {
            d0[r] = __ldg(&s0[r]);
            d1[r] = __ldg(&s1[r]);
            d2[r] = __ldg(&s2[r]);
        }
        if (tid < CPM) b1s[tid] = __ldg(&bih1[m * CPM + tid]) + __ldg(&bhh1[m * CPM + tid]);
    }
    __syncthreads();

    // read-phase decode: thread tid owns output tid = b*16 + c
    const int b_out  = gb16 + (tid >> 4);
    const int c_glob = m * CPM + (tid & 15);

    const ulonglong2* W0u = (const ulonglong2*)W0s;
    const ulonglong2* WAu = (const ulonglong2*)WAs;
    const ulonglong2* WBu = (const ulonglong2*)WBs;
    const ulonglong2* H0u = (const ulonglong2*)Hs0;
    const ulonglong2* H1u = (const ulonglong2*)Hs1;
    const unsigned sd0 = (unsigned)__cvta_generic_to_shared(Hs0);
    const unsigned sd1 = (unsigned)__cvta_generic_to_shared(Hs1);

    u64 acc0[8][4], accA[8][4];

    // fused pass-1 chunk (k-quarter J): Whh0 + Wih1 share every hv load
#define MMA1_CHUNK(J)                                                            \
    {                                                                            \
        ulonglong2 w0q[4], waq[4];                                               \
        _Pragma("unroll")                                                        \
        for (int c = 0; c < 4; c++) {                                            \
            int row = cq * 4 + c;                                                \
            w0q[c] = W0u[row * 128 + (J) * 32 + lane];                           \
            waq[c] = WAu[row * 128 + (J) * 32 + lane];                           \
        }                                                                        \
        _Pragma("unroll")                                                        \
        for (int i = 0; i < 8; i++) {                                            \
            ulonglong2 hv = H0u[(o * 8 + i) * 128 + (J) * 32 + lane];            \
            _Pragma("unroll")                                                    \
            for (int c = 0; c < 4; c++) {                                        \
                acc0[i][c] = ffma2(hv.x, w0q[c].x, acc0[i][c]);                  \
                acc0[i][c] = ffma2(hv.y, w0q[c].y, acc0[i][c]);                  \
                accA[i][c] = ffma2(hv.x, waq[c].x, accA[i][c]);                  \
                accA[i][c] = ffma2(hv.y, waq[c].y, accA[i][c]);                  \
            }                                                                    \
        }                                                                        \
    }

    // pass-2 chunk: Whh1 · h1[s-3] into accA
#define MMA2_CHUNK(J)                                                            \
    {                                                                            \
        ulonglong2 wbq[4];                                                       \
        _Pragma("unroll")                                                        \
        for (int c = 0; c < 4; c++)                                              \
            wbq[c] = WBu[(cq * 4 + c) * 128 + (J) * 32 + lane];                  \
        _Pragma("unroll")                                                        \
        for (int i = 0; i < 8; i++) {                                            \
            ulonglong2 hv = H1u[(o * 8 + i) * 128 + (J) * 32 + lane];            \
            _Pragma("unroll")                                                    \
            for (int c = 0; c < 4; c++) {                                        \
                accA[i][c] = ffma2(hv.x, wbq[c].x, accA[i][c]);                  \
                accA[i][c] = ffma2(hv.y, wbq[c].y, accA[i][c]);                  \
            }                                                                    \
        }                                                                        \
    }

    // shfl-16 pre-reduce ACC -> RS rows of 16 (stride 17, conflict-free)
#define REDUCE_TO(RS, ACC)                                                       \
    _Pragma("unroll")                                                            \
    for (int i = 0; i < 8; i++)                                                  \
        _Pragma("unroll")                                                        \
        for (int c = 0; c < 4; c++) {                                            \
            float v = unpack_sum(ACC[i][c]);                                     \
            v += __shfl_xor_sync(0xffffffffu, v, 16);                            \
            if (lane < 16)                                                       \
                (RS)[((o * 8 + i) * 16 + cq * 4 + c) * 17 + lane] = v;           \
        }

    // stage one k-half (Q=0/1) of a 16-row state block (coalesced cp.async)
#define STAGE_HALF(SD, SRC, Q)                                                   \
    {                                                                            \
        _Pragma("unroll")                                                        \
        for (int r = 0; r < 4; r++) {                                            \
            int l   = r * NTHR + tid;          /* 0..1023 f4 within half */      \
            int b_l = l >> 6;                                                    \
            int c4  = l & 63;                                                    \
            size_t srcf4 = (size_t)(gb16 + b_l) * 128 + (Q) * 64 + c4;           \
            asm volatile("cp.async.cg.shared.global [%0], [%1], 16;\n"           \
                         :: "r"((SD) + (b_l * 128 + (Q) * 64 + c4) * 16),        \
                            "l"((SRC) + srcf4 * 4));                             \
        }                                                                        \
        asm volatile("cp.async.commit_group;\n");                                \
    }

    for (int s = 1; s <= T_N + 1; s++) {
        const bool doH0 = (s <= T_N);
        const bool doH1 = (s >= 2);

        // ---- gather input-projection value early (independent) ----
        float xw = 0.f;
        if (doH0) {
            int tok = __ldg(&input[(s - 1) * B_N + b_out]);
            xw = __ldcg(&g_embW0[(size_t)tok * H_N + c_glob]);
        }

        // ---- barrier: wait 32 members' flags >= s-1 ----
        if (w == 0) {
            const unsigned* fp = &g_flag[(grp * GC + lane) * 8];
            unsigned v;
            do {
                asm volatile("ld.relaxed.gpu.global.u32 %0, [%1];"
                             : "=r"(v) : "l"(fp) : "memory");
            } while (__any_sync(0xffffffffu, v < (unsigned)(s - 1)));
            __threadfence();
        }
        __syncthreads();

        // ---- stage h0[s-2] and h1[s-3]: 4 commit groups (k-halves) ----
        {
            const float* h0src = g_h0[s & 1];
            const float* h1src = g_h1[(s + 1) & 1];
            STAGE_HALF(sd0, h0src, 0)
            STAGE_HALF(sd0, h0src, 1)
            STAGE_HALF(sd1, h1src, 0)
            STAGE_HALF(sd1, h1src, 1)
        }

#pragma unroll
        for (int i = 0; i < 8; i++)
#pragma unroll
            for (int c = 0; c < 4; c++) { acc0[i][c] = 0ull; accA[i][c] = 0ull; }

        // ---- pass 1 (fused Whh0 + Wih1 on h0[s-2]) ----
        asm volatile("cp.async.wait_group 3;\n" ::: "memory");
        __syncthreads();
        MMA1_CHUNK(0)
        MMA1_CHUNK(1)
        asm volatile("cp.async.wait_group 2;\n" ::: "memory");
        __syncthreads();
        MMA1_CHUNK(2)
        MMA1_CHUNK(3)

        // ---- reduce0 + h0[s-1] store (L2 latency hides behind pass 2) ----
        REDUCE_TO(Rs0, acc0)
        __syncthreads();
        if (doH0) {
            float ssum = 0.f;
#pragma unroll
            for (int l = 0; l < 16; l++) ssum += Rs0[tid * 17 + l];
            __stcg(&g_h0[(s - 1) & 1][b_out * H_N + c_glob], tanhf(ssum + xw));
        }

        // ---- pass 2 (Whh1 on h1[s-3]) ----
        asm volatile("cp.async.wait_group 1;\n" ::: "memory");
        __syncthreads();
        MMA2_CHUNK(0)
        MMA2_CHUNK(1)
        asm volatile("cp.async.wait_group 0;\n" ::: "memory");
        __syncthreads();
        MMA2_CHUNK(2)
        MMA2_CHUNK(3)

        // ---- reduce1 + h1[s-2] store ----
        REDUCE_TO(Rs1, accA)
        __syncthreads();
        if (doH1) {
            float ssum = 0.f;
#pragma unroll
            for (int l = 0; l < 16; l++) ssum += Rs1[tid * 17 + l];
            float v = tanhf(ssum + b1s[tid & 15]);
            __stcg(&g_h1[s & 1][b_out * H_N + c_glob], v);
            if (s == T_N + 1) __stcg(&out[b_out * H_N + c_glob], v);
        }

        // ---- publish step ----
        __syncthreads();
        if (tid == 0)
            asm volatile("st.release.gpu.global.u32 [%0], %1;"
                         :: "l"(&g_flag[cid * 8]), "r"((unsigned)s) : "memory");
    }
#undef MMA1_CHUNK
#undef MMA2_CHUNK
#undef REDUCE_TO
#undef STAGE_HALF
}

// ---------------- launch ----------------
extern "C" void kernel_launch(void* const* d_in, const int* in_sizes, int n_in,
                              void* d_out, int out_size) {
    const int*   input = (const int*)  d_in[0];
    const float* emb   = (const float*)d_in[1];
    const float* Wih0  = (const float*)d_in[2];
    const float* Whh0  = (const float*)d_in[3];
    const float* bih0  = (const float*)d_in[4];
    const float* bhh0  = (const float*)d_in[5];
    const float* Wih1  = (const float*)d_in[6];
    const float* Whh1  = (const float*)d_in[7];
    const float* bih1  = (const float*)d_in[8];
    const float* bhh1  = (const float*)d_in[9];
    float* out = (float*)d_out;

    cudaFuncSetAttribute(rnn_kernel, cudaFuncAttributeMaxDynamicSharedMemorySize, SMEM_BYTES);

    reset_kernel<<<(B_N * H_N + 255) / 256, 256>>>();
    embw_kernel<<<dim3(H_N / 128, V_N / 128), 256>>>(emb, Wih0, bih0, bhh0);
    rnn_kernel<<<GRID_R, NTHR, SMEM_BYTES>>>(input, Whh0, Wih1, Whh1, bih1, bhh1, out);
}